// round 15
// baseline (speedup 1.0000x reference)
#include <cuda_runtime.h>
#include <cuda_fp16.h>
#include <cstdint>

#define NNODES 50000
#define EDGES  400000
#define DD     128
#define HH     256
#define LL     5
#define BOND_ROWS 13
#define NCODE  60

// ---------------- scratch (device globals; no allocation) ----------------
__device__ float g_agg[(size_t)NNODES * DD];
__device__ float g_y  [(size_t)NNODES * HH];
__device__ float g_z2 [(size_t)NNODES * DD];
__device__ float g_h  [(size_t)NNODES * DD];
__device__ float g_sum1[HH], g_sq1[HH];
__device__ float g_sum2[DD], g_sq2[DD];
__device__ float g_btab[NCODE * DD];
// CSR (built once per call; edge_index constant across layers)
__device__ int g_cnt[NNODES];
__device__ int g_off[NNODES + 1];
__device__ int g_cur[NNODES];
__device__ int g_pak[EDGES];      // src | (code<<18)

// ---------------- helpers ----------------
__device__ __forceinline__ float hfr(float a) {
    return __half2float(__float2half_rn(a));
}
__device__ __forceinline__ uint32_t packhf(float e0, float e1) {
    uint32_t r;
    asm("cvt.rn.f16x2.f32 %0, %1, %2;" : "=r"(r) : "f"(e1), "f"(e0));
    return r;
}
__device__ __forceinline__ void mma_f16(float* c, const uint32_t* a, const uint32_t* b) {
    asm volatile(
        "mma.sync.aligned.m16n8k16.row.col.f32.f16.f16.f32 "
        "{%0,%1,%2,%3}, {%4,%5,%6,%7}, {%8,%9}, {%0,%1,%2,%3};"
        : "+f"(c[0]), "+f"(c[1]), "+f"(c[2]), "+f"(c[3])
        : "r"(a[0]), "r"(a[1]), "r"(a[2]), "r"(a[3]), "r"(b[0]), "r"(b[1]));
}

// ---------------- CSR build (once per call) ----------------
__global__ void zero_cnt_kernel() {
    int i = blockIdx.x * blockDim.x + threadIdx.x;
    if (i < NNODES) g_cnt[i] = 0;
}
__global__ void hist_kernel(const int* __restrict__ dst) {
    int e = blockIdx.x * blockDim.x + threadIdx.x;
    if (e < EDGES) atomicAdd(&g_cnt[__ldg(dst + e)], 1);
}
__global__ void scan_kernel() {
    __shared__ int part[1024];
    const int CH = (NNODES + 1023) / 1024;
    int t = threadIdx.x;
    int base = t * CH;
    int s = 0;
    for (int i = 0; i < CH; ++i) {
        int n = base + i;
        if (n < NNODES) s += g_cnt[n];
    }
    part[t] = s;
    __syncthreads();
    for (int off = 1; off < 1024; off <<= 1) {
        int tmp = (t >= off) ? part[t - off] : 0;
        __syncthreads();
        if (t >= off) part[t] += tmp;
        __syncthreads();
    }
    int run = part[t] - s;
    for (int i = 0; i < CH; ++i) {
        int n = base + i;
        if (n < NNODES) {
            g_off[n] = run;
            g_cur[n] = run;
            run += g_cnt[n];
        }
    }
    if (t == 0) g_off[NNODES] = EDGES;
}
__global__ void scatter_kernel(const int* __restrict__ src,
                               const int* __restrict__ dst,
                               const int* __restrict__ ea) {
    int e = blockIdx.x * blockDim.x + threadIdx.x;
    if (e >= EDGES) return;
    int d = __ldg(dst + e);
    int code = (__ldg(ea + 3 * e) * 6 + __ldg(ea + 3 * e + 1)) * 2 + __ldg(ea + 3 * e + 2);
    int pos = atomicAdd(&g_cur[d], 1);
    g_pak[pos] = __ldg(src + e) | (code << 18);
}

// ---------------- per-layer small kernels ----------------
__global__ void bond_table_kernel(const float* __restrict__ bond) {
    int code = blockIdx.x;
    int d    = threadIdx.x;
    int a0 = code / 12, a1 = (code / 2) % 6, a2 = code & 1;
    g_btab[code * DD + d] = __ldg(bond + (size_t)a0 * DD + d)
                          + __ldg(bond + (size_t)(5 + a1) * DD + d)
                          + __ldg(bond + (size_t)(11 + a2) * DD + d);
}

// agg[n] = (1+eps[l])*h[n] + sum_{CSR(n)} relu(h[src]+btab[code])
__global__ void __launch_bounds__(256)
aggregate_kernel(const float* __restrict__ h, const float* __restrict__ eps,
                 int l, float* __restrict__ agg) {
    if (blockIdx.x == 0) {
        int t = threadIdx.x;
        if (t < HH) { g_sum1[t] = 0.f; g_sq1[t] = 0.f; }
        if (t < DD) { g_sum2[t] = 0.f; g_sq2[t] = 0.f; }
    }
    int n    = (blockIdx.x * blockDim.x + threadIdx.x) >> 5;
    int lane = threadIdx.x & 31;
    if (n >= NNODES) return;
    int e0 = __ldg(g_off + n), e1 = __ldg(g_off + n + 1);
    float4 acc = make_float4(0.f, 0.f, 0.f, 0.f);
    for (int e = e0; e < e1; ++e) {
        int p = __ldg(g_pak + e);
        int s = p & 0x3FFFF;
        int c = p >> 18;
        float4 v  = __ldg((const float4*)(h + (size_t)s * DD) + lane);
        float4 tb = __ldg((const float4*)(g_btab + (size_t)c * DD) + lane);
        acc.x += fmaxf(v.x + tb.x, 0.f);
        acc.y += fmaxf(v.y + tb.y, 0.f);
        acc.z += fmaxf(v.z + tb.z, 0.f);
        acc.w += fmaxf(v.w + tb.w, 0.f);
    }
    float ce = 1.f + __ldg(eps + l);
    float4 hv = __ldg((const float4*)(h + (size_t)n * DD) + lane);
    acc.x = fmaf(hv.x, ce, acc.x);
    acc.y = fmaf(hv.y, ce, acc.y);
    acc.z = fmaf(hv.z, ce, acc.z);
    acc.w = fmaf(hv.w, ce, acc.w);
    *((float4*)(agg + (size_t)n * DD) + lane) = acc;
}

// ------- 3x-f16 split tensor-core GEMM, double-buffered, fused stats -------
// C[M,NC] = act(A)[M,K] @ B[K,NC] + bias, act = BN1+ReLU when BNA.
// Tile: 128 x NB (NB = 128 or 64). NB=64 doubles the CTA count for small-NC
// GEMMs, fixing last-wave quantization (1.32 -> 2.64 waves).
template<int K, int NC, int NB, bool BNA>
__global__ void __launch_bounds__(256, 2)
gemm_tc_kernel(const float* __restrict__ A, const float* __restrict__ B,
               const float* __restrict__ bias, float* __restrict__ C, int M,
               const float* __restrict__ bsum, const float* __restrict__ bsq,
               const float* __restrict__ gam,  const float* __restrict__ bet,
               float* __restrict__ osum, float* __restrict__ osq) {
    constexpr int BM = 128, BK = 16, K2 = BK / 2;
    constexpr int NI = NB / 16;            // n-fragments per warp
    constexpr int KS = BNA ? K : 1;
    constexpr int CPG = NB / 4;            // B float4 col-groups per k-row
    __shared__ uint32_t AsH[2][K2][BM + 8];
    __shared__ uint32_t AsL[2][K2][BM + 8];
    __shared__ uint32_t BsH[2][K2][NB + 8];
    __shared__ uint32_t BsL[2][K2][NB + 8];
    __shared__ float ssc[KS], ssh[KS];

    int tid = threadIdx.x;
    if (BNA) {
        float invM = 1.f / (float)M;
        for (int k = tid; k < K; k += 256) {
            float mu  = bsum[k] * invM;
            float var = bsq[k] * invM - mu * mu;
            float s   = gam[k] * rsqrtf(var + 1e-5f);
            ssc[k] = s;
            ssh[k] = bet[k] - mu * s;
        }
        __syncthreads();
    }

    int bm = blockIdx.x * BM;
    int bn = blockIdx.y * NB;
    int lane = tid & 31;
    int warp = tid >> 5;
    int wm = (warp & 3) * 32;
    int wn = (warp >> 2) * (NB / 2);
    int g = lane >> 2;
    int t = lane & 3;

    float acc[2][NI][4];
#pragma unroll
    for (int mi = 0; mi < 2; ++mi)
#pragma unroll
        for (int ni = 0; ni < NI; ++ni)
#pragma unroll
            for (int j = 0; j < 4; ++j) acc[mi][ni][j] = 0.f;

    // B load map: thread tid (< 2*NB) loads rows 2*bp, 2*bp+1, cols bc*4..+3
    const int bp = tid / CPG;
    const int bc = tid % CPG;
    const bool bval = (tid < 2 * NB);
    const int rA0 = (tid * 2)     >> 2, cA0 = (tid * 2)     & 3;
    const int rA1 = (tid * 2 + 1) >> 2, cA1 = (tid * 2 + 1) & 3;

    float4 pa[2], pb0, pb1;

    auto ldg_tile = [&](int k0) {
        int gr0 = bm + rA0, gr1 = bm + rA1;
        pa[0] = (gr0 < M) ? __ldg((const float4*)(A + (size_t)gr0 * K + k0 + cA0 * 4))
                          : make_float4(0.f, 0.f, 0.f, 0.f);
        pa[1] = (gr1 < M) ? __ldg((const float4*)(A + (size_t)gr1 * K + k0 + cA1 * 4))
                          : make_float4(0.f, 0.f, 0.f, 0.f);
        if (bval) {
            pb0 = __ldg((const float4*)(B + (size_t)(k0 + 2 * bp)     * NC + bn + bc * 4));
            pb1 = __ldg((const float4*)(B + (size_t)(k0 + 2 * bp + 1) * NC + bn + bc * 4));
        }
    };

    auto store_tile = [&](int s, int k0) {
#pragma unroll
        for (int it = 0; it < 2; ++it) {
            int r  = it ? rA1 : rA0;
            int c4 = it ? cA1 : cA0;
            float4 v = pa[it];
            if (BNA) {
                int kk = k0 + c4 * 4;
                v.x = fmaxf(fmaf(v.x, ssc[kk + 0], ssh[kk + 0]), 0.f);
                v.y = fmaxf(fmaf(v.y, ssc[kk + 1], ssh[kk + 1]), 0.f);
                v.z = fmaxf(fmaf(v.z, ssc[kk + 2], ssh[kk + 2]), 0.f);
                v.w = fmaxf(fmaf(v.w, ssc[kk + 3], ssh[kk + 3]), 0.f);
            }
            float h0 = hfr(v.x), h1 = hfr(v.y), h2 = hfr(v.z), h3 = hfr(v.w);
            AsH[s][c4 * 2 + 0][r] = packhf(h0, h1);
            AsH[s][c4 * 2 + 1][r] = packhf(h2, h3);
            AsL[s][c4 * 2 + 0][r] = packhf(v.x - h0, v.y - h1);
            AsL[s][c4 * 2 + 1][r] = packhf(v.z - h2, v.w - h3);
        }
        if (bval) {
            float bh0 = hfr(pb0.x), bh1 = hfr(pb0.y), bh2 = hfr(pb0.z), bh3 = hfr(pb0.w);
            float ch0 = hfr(pb1.x), ch1 = hfr(pb1.y), ch2 = hfr(pb1.z), ch3 = hfr(pb1.w);
            uint4 uh, ul;
            uh.x = packhf(bh0, ch0); uh.y = packhf(bh1, ch1);
            uh.z = packhf(bh2, ch2); uh.w = packhf(bh3, ch3);
            ul.x = packhf(pb0.x - bh0, pb1.x - ch0);
            ul.y = packhf(pb0.y - bh1, pb1.y - ch1);
            ul.z = packhf(pb0.z - bh2, pb1.z - ch2);
            ul.w = packhf(pb0.w - bh3, pb1.w - ch3);
            *(uint4*)&BsH[s][bp][bc * 4] = uh;
            *(uint4*)&BsL[s][bp][bc * 4] = ul;
        }
    };

    ldg_tile(0);
    store_tile(0, 0);
    __syncthreads();

    int s = 0;
    for (int k0 = 0; k0 < K; k0 += BK) {
        int kn = k0 + BK;
        if (kn < K) ldg_tile(kn);

        uint32_t ah[2][4], al[2][4];
#pragma unroll
        for (int mi = 0; mi < 2; ++mi) {
            int row = wm + mi * 16 + g;
            ah[mi][0] = AsH[s][t][row];     ah[mi][1] = AsH[s][t][row + 8];
            ah[mi][2] = AsH[s][t + 4][row]; ah[mi][3] = AsH[s][t + 4][row + 8];
            al[mi][0] = AsL[s][t][row];     al[mi][1] = AsL[s][t][row + 8];
            al[mi][2] = AsL[s][t + 4][row]; al[mi][3] = AsL[s][t + 4][row + 8];
        }
        uint32_t bh[NI][2], bl[NI][2];
#pragma unroll
        for (int ni = 0; ni < NI; ++ni) {
            int col = wn + ni * 8 + g;
            bh[ni][0] = BsH[s][t][col]; bh[ni][1] = BsH[s][t + 4][col];
            bl[ni][0] = BsL[s][t][col]; bl[ni][1] = BsL[s][t + 4][col];
        }
#pragma unroll
        for (int ni = 0; ni < NI; ++ni)
#pragma unroll
            for (int mi = 0; mi < 2; ++mi)
                mma_f16(acc[mi][ni], ah[mi], bl[ni]);
#pragma unroll
        for (int ni = 0; ni < NI; ++ni)
#pragma unroll
            for (int mi = 0; mi < 2; ++mi)
                mma_f16(acc[mi][ni], al[mi], bh[ni]);
#pragma unroll
        for (int ni = 0; ni < NI; ++ni)
#pragma unroll
            for (int mi = 0; mi < 2; ++mi)
                mma_f16(acc[mi][ni], ah[mi], bh[ni]);

        if (kn < K) store_tile(s ^ 1, kn);
        __syncthreads();
        s ^= 1;
    }

#pragma unroll
    for (int ni = 0; ni < NI; ++ni) {
        int col = bn + wn + ni * 8 + 2 * t;
        float bx = __ldg(bias + col), by = __ldg(bias + col + 1);
        float s0 = 0.f, q0 = 0.f, s1 = 0.f, q1 = 0.f;
#pragma unroll
        for (int mi = 0; mi < 2; ++mi) {
            int row0 = bm + wm + mi * 16 + g;
            int row1 = row0 + 8;
            if (row0 < M) {
                float v0 = acc[mi][ni][0] + bx;
                float v1 = acc[mi][ni][1] + by;
                *(float2*)(C + (size_t)row0 * NC + col) = make_float2(v0, v1);
                s0 += v0; q0 = fmaf(v0, v0, q0);
                s1 += v1; q1 = fmaf(v1, v1, q1);
            }
            if (row1 < M) {
                float v2 = acc[mi][ni][2] + bx;
                float v3 = acc[mi][ni][3] + by;
                *(float2*)(C + (size_t)row1 * NC + col) = make_float2(v2, v3);
                s0 += v2; q0 = fmaf(v2, v2, q0);
                s1 += v3; q1 = fmaf(v3, v3, q1);
            }
        }
#pragma unroll
        for (int o = 4; o < 32; o <<= 1) {
            s0 += __shfl_xor_sync(0xFFFFFFFF, s0, o);
            q0 += __shfl_xor_sync(0xFFFFFFFF, q0, o);
            s1 += __shfl_xor_sync(0xFFFFFFFF, s1, o);
            q1 += __shfl_xor_sync(0xFFFFFFFF, q1, o);
        }
        if (g == 0) {
            atomicAdd(osum + col,     s0);
            atomicAdd(osq  + col,     q0);
            atomicAdd(osum + col + 1, s1);
            atomicAdd(osq  + col + 1, q1);
        }
    }
}

// out = bn2(z2) [+ relu]; smem-staged scale/shift
__global__ void __launch_bounds__(256)
bn2_apply_kernel(const float* __restrict__ z,
                 float* __restrict__ out,
                 const float* __restrict__ gam,
                 const float* __restrict__ bet,
                 int do_relu, float invM) {
    __shared__ float sc[DD], sh[DD];
    int tid = threadIdx.x;
    if (tid < DD) {
        float mu  = g_sum2[tid] * invM;
        float var = g_sq2[tid] * invM - mu * mu;
        float s   = __ldg(gam + tid) * rsqrtf(var + 1e-5f);
        sc[tid] = s;
        sh[tid] = __ldg(bet + tid) - mu * s;
    }
    __syncthreads();
    const int n4 = NNODES * DD / 4;
    int base = blockIdx.x * 1024;
#pragma unroll
    for (int j = 0; j < 4; ++j) {
        int i = base + j * 256 + tid;
        if (i >= n4) break;
        int c = (i & (DD / 4 - 1)) << 2;
        float4 v = __ldg((const float4*)z + i);
        v.x = fmaf(v.x, sc[c + 0], sh[c + 0]);
        v.y = fmaf(v.y, sc[c + 1], sh[c + 1]);
        v.z = fmaf(v.z, sc[c + 2], sh[c + 2]);
        v.w = fmaf(v.w, sc[c + 3], sh[c + 3]);
        if (do_relu) {
            v.x = fmaxf(v.x, 0.f); v.y = fmaxf(v.y, 0.f);
            v.z = fmaxf(v.z, 0.f); v.w = fmaxf(v.w, 0.f);
        }
        ((float4*)out)[i] = v;
    }
}

// ---------------- host launcher ----------------
extern "C" void kernel_launch(void* const* d_in, const int* in_sizes, int n_in,
                              void* d_out, int out_size) {
    const float* x    = (const float*)d_in[0];
    const int*   ei   = (const int*)  d_in[1];
    const int*   ea   = (const int*)  d_in[2];
    const float* W1   = (const float*)d_in[3];
    const float* b1   = (const float*)d_in[4];
    const float* g1   = (const float*)d_in[5];
    const float* bb1  = (const float*)d_in[6];
    const float* W2   = (const float*)d_in[7];
    const float* b2   = (const float*)d_in[8];
    const float* eps  = (const float*)d_in[9];
    const float* bond = (const float*)d_in[10];
    const float* g2   = (const float*)d_in[11];
    const float* bb2  = (const float*)d_in[12];
    float* out = (float*)d_out;

    float *p_agg, *p_y, *p_z2, *p_h;
    float *p_sum1, *p_sq1, *p_sum2, *p_sq2;
    cudaGetSymbolAddress((void**)&p_agg,  g_agg);
    cudaGetSymbolAddress((void**)&p_y,    g_y);
    cudaGetSymbolAddress((void**)&p_z2,   g_z2);
    cudaGetSymbolAddress((void**)&p_h,    g_h);
    cudaGetSymbolAddress((void**)&p_sum1, g_sum1);
    cudaGetSymbolAddress((void**)&p_sq1,  g_sq1);
    cudaGetSymbolAddress((void**)&p_sum2, g_sum2);
    cudaGetSymbolAddress((void**)&p_sq2,  g_sq2);

    const int M = NNODES;
    const int agg_blocks = (NNODES * 32 + 255) / 256;
    const int bn_blocks  = (NNODES * DD / 4 + 1023) / 1024;
    const dim3 g1grid((M + 127) / 128, HH / 128);   // 391 x 2 (NB=128)
    const dim3 g2grid((M + 127) / 128, DD / 64);    // 391 x 2 (NB=64)
    const float invM = 1.f / (float)M;

    // ---- CSR build (edge_index identical across layers) ----
    zero_cnt_kernel<<<(NNODES + 255) / 256, 256>>>();
    hist_kernel<<<(EDGES + 255) / 256, 256>>>(ei + EDGES);
    scan_kernel<<<1, 1024>>>();
    scatter_kernel<<<(EDGES + 255) / 256, 256>>>(ei, ei + EDGES, ea);

    const float* hcur = x;
    for (int l = 0; l < LL; ++l) {
        bond_table_kernel<<<NCODE, DD>>>(bond + (size_t)l * BOND_ROWS * DD);
        aggregate_kernel<<<agg_blocks, 256>>>(hcur, eps, l, p_agg);
        // GEMM1 (3x-f16 TC, NB=128, fused BN1 stats): y = agg @ W1[l] + b1[l]
        gemm_tc_kernel<DD, HH, 128, false><<<g1grid, 256>>>(
            p_agg, W1 + (size_t)l * DD * HH, b1 + (size_t)l * HH, p_y, M,
            nullptr, nullptr, nullptr, nullptr, p_sum1, p_sq1);
        // GEMM2 (3x-f16 TC, NB=64 -> 782 CTAs, fused BN1+ReLU, BN2 stats)
        gemm_tc_kernel<HH, DD, 64, true><<<g2grid, 256>>>(
            p_y, W2 + (size_t)l * HH * DD, b2 + (size_t)l * DD, p_z2, M,
            p_sum1, p_sq1, g1 + (size_t)l * HH, bb1 + (size_t)l * HH,
            p_sum2, p_sq2);
        bool last = (l == LL - 1);
        bn2_apply_kernel<<<bn_blocks, 256>>>(
            p_z2, last ? out : p_h,
            g2 + (size_t)l * DD, bb2 + (size_t)l * DD,
            last ? 0 : 1, invM);
        hcur = p_h;
    }
}

// round 16
// speedup vs baseline: 1.1648x; 1.1648x over previous
#include <cuda_runtime.h>
#include <cuda_fp16.h>
#include <cstdint>

#define NNODES 50000
#define EDGES  400000
#define DD     128
#define HH     256
#define LL     5
#define BOND_ROWS 13
#define NCODE  60

// ---------------- scratch (device globals; no allocation) ----------------
__device__ float g_agg[(size_t)NNODES * DD];
__device__ float g_y  [(size_t)NNODES * HH];
__device__ float g_z2 [(size_t)NNODES * DD];
__device__ float g_h  [(size_t)NNODES * DD];
__device__ float g_sum1[HH], g_sq1[HH];
__device__ float g_sum2[DD], g_sq2[DD];
__device__ float g_btab[NCODE * DD];
// CSR (built once per call; edge_index constant across layers)
__device__ int g_cnt[NNODES];
__device__ int g_off[NNODES + 1];
__device__ int g_cur[NNODES];
__device__ int g_pak[EDGES];      // src | (code<<18)

// ---------------- helpers ----------------
__device__ __forceinline__ float hfr(float a) {
    return __half2float(__float2half_rn(a));
}
__device__ __forceinline__ uint32_t packhf(float e0, float e1) {
    uint32_t r;
    asm("cvt.rn.f16x2.f32 %0, %1, %2;" : "=r"(r) : "f"(e1), "f"(e0));
    return r;
}
__device__ __forceinline__ void mma_f16(float* c, const uint32_t* a, const uint32_t* b) {
    asm volatile(
        "mma.sync.aligned.m16n8k16.row.col.f32.f16.f16.f32 "
        "{%0,%1,%2,%3}, {%4,%5,%6,%7}, {%8,%9}, {%0,%1,%2,%3};"
        : "+f"(c[0]), "+f"(c[1]), "+f"(c[2]), "+f"(c[3])
        : "r"(a[0]), "r"(a[1]), "r"(a[2]), "r"(a[3]), "r"(b[0]), "r"(b[1]));
}

// ---------------- CSR build (once per call) ----------------
__global__ void zero_cnt_kernel() {
    int i = blockIdx.x * blockDim.x + threadIdx.x;
    if (i < NNODES) g_cnt[i] = 0;
}
__global__ void hist_kernel(const int* __restrict__ dst) {
    int e = blockIdx.x * blockDim.x + threadIdx.x;
    if (e < EDGES) atomicAdd(&g_cnt[__ldg(dst + e)], 1);
}
__global__ void scan_kernel() {
    __shared__ int part[1024];
    const int CH = (NNODES + 1023) / 1024;
    int t = threadIdx.x;
    int base = t * CH;
    int s = 0;
    for (int i = 0; i < CH; ++i) {
        int n = base + i;
        if (n < NNODES) s += g_cnt[n];
    }
    part[t] = s;
    __syncthreads();
    for (int off = 1; off < 1024; off <<= 1) {
        int tmp = (t >= off) ? part[t - off] : 0;
        __syncthreads();
        if (t >= off) part[t] += tmp;
        __syncthreads();
    }
    int run = part[t] - s;
    for (int i = 0; i < CH; ++i) {
        int n = base + i;
        if (n < NNODES) {
            g_off[n] = run;
            g_cur[n] = run;
            run += g_cnt[n];
        }
    }
    if (t == 0) g_off[NNODES] = EDGES;
}
__global__ void scatter_kernel(const int* __restrict__ src,
                               const int* __restrict__ dst,
                               const int* __restrict__ ea) {
    int e = blockIdx.x * blockDim.x + threadIdx.x;
    if (e >= EDGES) return;
    int d = __ldg(dst + e);
    int code = (__ldg(ea + 3 * e) * 6 + __ldg(ea + 3 * e + 1)) * 2 + __ldg(ea + 3 * e + 2);
    int pos = atomicAdd(&g_cur[d], 1);
    g_pak[pos] = __ldg(src + e) | (code << 18);
}

// ---------------- per-layer small kernels ----------------
__global__ void bond_table_kernel(const float* __restrict__ bond) {
    int code = blockIdx.x;
    int d    = threadIdx.x;
    int a0 = code / 12, a1 = (code / 2) % 6, a2 = code & 1;
    g_btab[code * DD + d] = __ldg(bond + (size_t)a0 * DD + d)
                          + __ldg(bond + (size_t)(5 + a1) * DD + d)
                          + __ldg(bond + (size_t)(11 + a2) * DD + d);
}

// agg[n] = (1+eps[l])*h[n] + sum_{CSR(n)} relu(h[src]+btab[code])
__global__ void __launch_bounds__(256)
aggregate_kernel(const float* __restrict__ h, const float* __restrict__ eps,
                 int l, float* __restrict__ agg) {
    if (blockIdx.x == 0) {
        int t = threadIdx.x;
        if (t < HH) { g_sum1[t] = 0.f; g_sq1[t] = 0.f; }
        if (t < DD) { g_sum2[t] = 0.f; g_sq2[t] = 0.f; }
    }
    int n    = (blockIdx.x * blockDim.x + threadIdx.x) >> 5;
    int lane = threadIdx.x & 31;
    if (n >= NNODES) return;
    int e0 = __ldg(g_off + n), e1 = __ldg(g_off + n + 1);
    float4 acc = make_float4(0.f, 0.f, 0.f, 0.f);
    for (int e = e0; e < e1; ++e) {
        int p = __ldg(g_pak + e);
        int s = p & 0x3FFFF;
        int c = p >> 18;
        float4 v  = __ldg((const float4*)(h + (size_t)s * DD) + lane);
        float4 tb = __ldg((const float4*)(g_btab + (size_t)c * DD) + lane);
        acc.x += fmaxf(v.x + tb.x, 0.f);
        acc.y += fmaxf(v.y + tb.y, 0.f);
        acc.z += fmaxf(v.z + tb.z, 0.f);
        acc.w += fmaxf(v.w + tb.w, 0.f);
    }
    float ce = 1.f + __ldg(eps + l);
    float4 hv = __ldg((const float4*)(h + (size_t)n * DD) + lane);
    acc.x = fmaf(hv.x, ce, acc.x);
    acc.y = fmaf(hv.y, ce, acc.y);
    acc.z = fmaf(hv.z, ce, acc.z);
    acc.w = fmaf(hv.w, ce, acc.w);
    *((float4*)(agg + (size_t)n * DD) + lane) = acc;
}

// ------- 3x-f16 split tensor-core GEMM, double-buffered, fused stats -------
// C[M,NC] = act(A)[M,K] @ B[K,NC] + bias, act = BN1+ReLU when BNA.
// Tile: BM x 128. BM=128: 4m x 2n warps (NI=8). BM=64: 2m x 4n warps (NI=4),
// doubling CTA count for GEMM2 (fixes 1.32-wave quantization on the M axis;
// per-CTA mma count stays equal to a GEMM1 CTA).
template<int K, int NC, int BM, bool BNA>
__global__ void __launch_bounds__(256, 2)
gemm_tc_kernel(const float* __restrict__ A, const float* __restrict__ B,
               const float* __restrict__ bias, float* __restrict__ C, int M,
               const float* __restrict__ bsum, const float* __restrict__ bsq,
               const float* __restrict__ gam,  const float* __restrict__ bet,
               float* __restrict__ osum, float* __restrict__ osq) {
    constexpr int BN = 128, BK = 16, K2 = BK / 2;
    constexpr int MWARPS = BM / 32;              // 4 (BM=128) or 2 (BM=64)
    constexpr int NWARPS = 8 / MWARPS;           // 2 or 4
    constexpr int WNEXT  = BN / NWARPS;          // warp n-extent: 64 or 32
    constexpr int NI     = WNEXT / 8;            // 8 or 4
    constexpr int APT    = BM * 4 / 256;         // A float4 per thread: 2 or 1
    constexpr int KS = BNA ? K : 1;
    __shared__ uint32_t AsH[2][K2][BM + 8];
    __shared__ uint32_t AsL[2][K2][BM + 8];
    __shared__ uint32_t BsH[2][K2][BN + 8];
    __shared__ uint32_t BsL[2][K2][BN + 8];
    __shared__ float ssc[KS], ssh[KS];

    int tid = threadIdx.x;
    if (BNA) {
        float invM = 1.f / (float)M;
        for (int k = tid; k < K; k += 256) {
            float mu  = bsum[k] * invM;
            float var = bsq[k] * invM - mu * mu;
            float s   = gam[k] * rsqrtf(var + 1e-5f);
            ssc[k] = s;
            ssh[k] = bet[k] - mu * s;
        }
        __syncthreads();
    }

    int bm = blockIdx.x * BM;
    int bn = blockIdx.y * BN;
    int lane = tid & 31;
    int warp = tid >> 5;
    int wm = (warp % MWARPS) * 32;
    int wn = (warp / MWARPS) * WNEXT;
    int g = lane >> 2;
    int t = lane & 3;

    float acc[2][NI][4];
#pragma unroll
    for (int mi = 0; mi < 2; ++mi)
#pragma unroll
        for (int ni = 0; ni < NI; ++ni)
#pragma unroll
            for (int j = 0; j < 4; ++j) acc[mi][ni][j] = 0.f;

    const int k2r = tid >> 5;
    const int cg  = tid & 31;

    float4 pa[APT], pb0, pb1;

    auto ldg_tile = [&](int k0) {
#pragma unroll
        for (int it = 0; it < APT; ++it) {
            int f4 = tid * APT + it;
            int r = f4 >> 2, c4 = f4 & 3;
            int gr = bm + r;
            pa[it] = (gr < M) ? __ldg((const float4*)(A + (size_t)gr * K + k0 + c4 * 4))
                              : make_float4(0.f, 0.f, 0.f, 0.f);
        }
        pb0 = __ldg((const float4*)(B + (size_t)(k0 + 2 * k2r)     * NC + bn + cg * 4));
        pb1 = __ldg((const float4*)(B + (size_t)(k0 + 2 * k2r + 1) * NC + bn + cg * 4));
    };

    auto store_tile = [&](int s, int k0) {
#pragma unroll
        for (int it = 0; it < APT; ++it) {
            int f4 = tid * APT + it;
            int r = f4 >> 2, c4 = f4 & 3;
            float4 v = pa[it];
            if (BNA) {
                int kk = k0 + c4 * 4;
                v.x = fmaxf(fmaf(v.x, ssc[kk + 0], ssh[kk + 0]), 0.f);
                v.y = fmaxf(fmaf(v.y, ssc[kk + 1], ssh[kk + 1]), 0.f);
                v.z = fmaxf(fmaf(v.z, ssc[kk + 2], ssh[kk + 2]), 0.f);
                v.w = fmaxf(fmaf(v.w, ssc[kk + 3], ssh[kk + 3]), 0.f);
            }
            float h0 = hfr(v.x), h1 = hfr(v.y), h2 = hfr(v.z), h3 = hfr(v.w);
            AsH[s][c4 * 2 + 0][r] = packhf(h0, h1);
            AsH[s][c4 * 2 + 1][r] = packhf(h2, h3);
            AsL[s][c4 * 2 + 0][r] = packhf(v.x - h0, v.y - h1);
            AsL[s][c4 * 2 + 1][r] = packhf(v.z - h2, v.w - h3);
        }
        float bh0 = hfr(pb0.x), bh1 = hfr(pb0.y), bh2 = hfr(pb0.z), bh3 = hfr(pb0.w);
        float ch0 = hfr(pb1.x), ch1 = hfr(pb1.y), ch2 = hfr(pb1.z), ch3 = hfr(pb1.w);
        uint4 uh, ul;
        uh.x = packhf(bh0, ch0); uh.y = packhf(bh1, ch1);
        uh.z = packhf(bh2, ch2); uh.w = packhf(bh3, ch3);
        ul.x = packhf(pb0.x - bh0, pb1.x - ch0);
        ul.y = packhf(pb0.y - bh1, pb1.y - ch1);
        ul.z = packhf(pb0.z - bh2, pb1.z - ch2);
        ul.w = packhf(pb0.w - bh3, pb1.w - ch3);
        *(uint4*)&BsH[s][k2r][cg * 4] = uh;
        *(uint4*)&BsL[s][k2r][cg * 4] = ul;
    };

    ldg_tile(0);
    store_tile(0, 0);
    __syncthreads();

    int s = 0;
    for (int k0 = 0; k0 < K; k0 += BK) {
        int kn = k0 + BK;
        if (kn < K) ldg_tile(kn);

        uint32_t ah[2][4], al[2][4];
#pragma unroll
        for (int mi = 0; mi < 2; ++mi) {
            int row = wm + mi * 16 + g;
            ah[mi][0] = AsH[s][t][row];     ah[mi][1] = AsH[s][t][row + 8];
            ah[mi][2] = AsH[s][t + 4][row]; ah[mi][3] = AsH[s][t + 4][row + 8];
            al[mi][0] = AsL[s][t][row];     al[mi][1] = AsL[s][t][row + 8];
            al[mi][2] = AsL[s][t + 4][row]; al[mi][3] = AsL[s][t + 4][row + 8];
        }
        uint32_t bh[NI][2], bl[NI][2];
#pragma unroll
        for (int ni = 0; ni < NI; ++ni) {
            int col = wn + ni * 8 + g;
            bh[ni][0] = BsH[s][t][col]; bh[ni][1] = BsH[s][t + 4][col];
            bl[ni][0] = BsL[s][t][col]; bl[ni][1] = BsL[s][t + 4][col];
        }
#pragma unroll
        for (int ni = 0; ni < NI; ++ni)
#pragma unroll
            for (int mi = 0; mi < 2; ++mi)
                mma_f16(acc[mi][ni], ah[mi], bl[ni]);
#pragma unroll
        for (int ni = 0; ni < NI; ++ni)
#pragma unroll
            for (int mi = 0; mi < 2; ++mi)
                mma_f16(acc[mi][ni], al[mi], bh[ni]);
#pragma unroll
        for (int ni = 0; ni < NI; ++ni)
#pragma unroll
            for (int mi = 0; mi < 2; ++mi)
                mma_f16(acc[mi][ni], ah[mi], bh[ni]);

        if (kn < K) store_tile(s ^ 1, kn);
        __syncthreads();
        s ^= 1;
    }

#pragma unroll
    for (int ni = 0; ni < NI; ++ni) {
        int col = bn + wn + ni * 8 + 2 * t;
        float bx = __ldg(bias + col), by = __ldg(bias + col + 1);
        float s0 = 0.f, q0 = 0.f, s1 = 0.f, q1 = 0.f;
#pragma unroll
        for (int mi = 0; mi < 2; ++mi) {
            int row0 = bm + wm + mi * 16 + g;
            int row1 = row0 + 8;
            if (row0 < M) {
                float v0 = acc[mi][ni][0] + bx;
                float v1 = acc[mi][ni][1] + by;
                *(float2*)(C + (size_t)row0 * NC + col) = make_float2(v0, v1);
                s0 += v0; q0 = fmaf(v0, v0, q0);
                s1 += v1; q1 = fmaf(v1, v1, q1);
            }
            if (row1 < M) {
                float v2 = acc[mi][ni][2] + bx;
                float v3 = acc[mi][ni][3] + by;
                *(float2*)(C + (size_t)row1 * NC + col) = make_float2(v2, v3);
                s0 += v2; q0 = fmaf(v2, v2, q0);
                s1 += v3; q1 = fmaf(v3, v3, q1);
            }
        }
#pragma unroll
        for (int o = 4; o < 32; o <<= 1) {
            s0 += __shfl_xor_sync(0xFFFFFFFF, s0, o);
            q0 += __shfl_xor_sync(0xFFFFFFFF, q0, o);
            s1 += __shfl_xor_sync(0xFFFFFFFF, s1, o);
            q1 += __shfl_xor_sync(0xFFFFFFFF, q1, o);
        }
        if (g == 0) {
            atomicAdd(osum + col,     s0);
            atomicAdd(osq  + col,     q0);
            atomicAdd(osum + col + 1, s1);
            atomicAdd(osq  + col + 1, q1);
        }
    }
}

// out = bn2(z2) [+ relu]; smem-staged scale/shift
__global__ void __launch_bounds__(256)
bn2_apply_kernel(const float* __restrict__ z,
                 float* __restrict__ out,
                 const float* __restrict__ gam,
                 const float* __restrict__ bet,
                 int do_relu, float invM) {
    __shared__ float sc[DD], sh[DD];
    int tid = threadIdx.x;
    if (tid < DD) {
        float mu  = g_sum2[tid] * invM;
        float var = g_sq2[tid] * invM - mu * mu;
        float s   = __ldg(gam + tid) * rsqrtf(var + 1e-5f);
        sc[tid] = s;
        sh[tid] = __ldg(bet + tid) - mu * s;
    }
    __syncthreads();
    const int n4 = NNODES * DD / 4;
    int base = blockIdx.x * 1024;
#pragma unroll
    for (int j = 0; j < 4; ++j) {
        int i = base + j * 256 + tid;
        if (i >= n4) break;
        int c = (i & (DD / 4 - 1)) << 2;
        float4 v = __ldg((const float4*)z + i);
        v.x = fmaf(v.x, sc[c + 0], sh[c + 0]);
        v.y = fmaf(v.y, sc[c + 1], sh[c + 1]);
        v.z = fmaf(v.z, sc[c + 2], sh[c + 2]);
        v.w = fmaf(v.w, sc[c + 3], sh[c + 3]);
        if (do_relu) {
            v.x = fmaxf(v.x, 0.f); v.y = fmaxf(v.y, 0.f);
            v.z = fmaxf(v.z, 0.f); v.w = fmaxf(v.w, 0.f);
        }
        ((float4*)out)[i] = v;
    }
}

// ---------------- host launcher ----------------
extern "C" void kernel_launch(void* const* d_in, const int* in_sizes, int n_in,
                              void* d_out, int out_size) {
    const float* x    = (const float*)d_in[0];
    const int*   ei   = (const int*)  d_in[1];
    const int*   ea   = (const int*)  d_in[2];
    const float* W1   = (const float*)d_in[3];
    const float* b1   = (const float*)d_in[4];
    const float* g1   = (const float*)d_in[5];
    const float* bb1  = (const float*)d_in[6];
    const float* W2   = (const float*)d_in[7];
    const float* b2   = (const float*)d_in[8];
    const float* eps  = (const float*)d_in[9];
    const float* bond = (const float*)d_in[10];
    const float* g2   = (const float*)d_in[11];
    const float* bb2  = (const float*)d_in[12];
    float* out = (float*)d_out;

    float *p_agg, *p_y, *p_z2, *p_h;
    float *p_sum1, *p_sq1, *p_sum2, *p_sq2;
    cudaGetSymbolAddress((void**)&p_agg,  g_agg);
    cudaGetSymbolAddress((void**)&p_y,    g_y);
    cudaGetSymbolAddress((void**)&p_z2,   g_z2);
    cudaGetSymbolAddress((void**)&p_h,    g_h);
    cudaGetSymbolAddress((void**)&p_sum1, g_sum1);
    cudaGetSymbolAddress((void**)&p_sq1,  g_sq1);
    cudaGetSymbolAddress((void**)&p_sum2, g_sum2);
    cudaGetSymbolAddress((void**)&p_sq2,  g_sq2);

    const int M = NNODES;
    const int agg_blocks = (NNODES * 32 + 255) / 256;
    const int bn_blocks  = (NNODES * DD / 4 + 1023) / 1024;
    const dim3 g1grid((M + 127) / 128, HH / 128);   // 391 x 2 (BM=128)
    const dim3 g2grid((M + 63) / 64, DD / 128);     // 782 x 1 (BM=64)
    const float invM = 1.f / (float)M;

    // ---- CSR build (edge_index identical across layers) ----
    zero_cnt_kernel<<<(NNODES + 255) / 256, 256>>>();
    hist_kernel<<<(EDGES + 255) / 256, 256>>>(ei + EDGES);
    scan_kernel<<<1, 1024>>>();
    scatter_kernel<<<(EDGES + 255) / 256, 256>>>(ei, ei + EDGES, ea);

    const float* hcur = x;
    for (int l = 0; l < LL; ++l) {
        bond_table_kernel<<<NCODE, DD>>>(bond + (size_t)l * BOND_ROWS * DD);
        aggregate_kernel<<<agg_blocks, 256>>>(hcur, eps, l, p_agg);
        // GEMM1 (3x-f16 TC, BM=128, fused BN1 stats): y = agg @ W1[l] + b1[l]
        gemm_tc_kernel<DD, HH, 128, false><<<g1grid, 256>>>(
            p_agg, W1 + (size_t)l * DD * HH, b1 + (size_t)l * HH, p_y, M,
            nullptr, nullptr, nullptr, nullptr, p_sum1, p_sq1);
        // GEMM2 (3x-f16 TC, BM=64 -> 782 CTAs, fused BN1+ReLU, BN2 stats)
        gemm_tc_kernel<HH, DD, 64, true><<<g2grid, 256>>>(
            p_y, W2 + (size_t)l * HH * DD, b2 + (size_t)l * DD, p_z2, M,
            p_sum1, p_sq1, g1 + (size_t)l * HH, bb1 + (size_t)l * HH,
            p_sum2, p_sq2);
        bool last = (l == LL - 1);
        bn2_apply_kernel<<<bn_blocks, 256>>>(
            p_z2, last ? out : p_h,
            g2 + (size_t)l * DD, bb2 + (size_t)l * DD,
            last ? 0 : 1, invM);
        hcur = p_h;
    }
}

// round 17
// speedup vs baseline: 1.2050x; 1.0345x over previous
#include <cuda_runtime.h>
#include <cuda_fp16.h>
#include <cstdint>

#define NNODES 50000
#define EDGES  400000
#define DD     128
#define HH     256
#define LL     5
#define BOND_ROWS 13
#define NCODE  60

// ---------------- scratch (device globals; no allocation) ----------------
__device__ float g_agg[(size_t)NNODES * DD];
__device__ float g_y  [(size_t)NNODES * HH];
__device__ float g_z2 [(size_t)NNODES * DD];
__device__ float g_h  [(size_t)NNODES * DD];
__device__ float g_sum1[HH], g_sq1[HH];
__device__ float g_sum2[DD], g_sq2[DD];
__device__ float g_btab[LL * NCODE * DD];   // all layers precomputed
// CSR (built once per call; edge_index constant across layers)
__device__ int g_cnt[NNODES];
__device__ int g_off[NNODES + 1];
__device__ int g_cur[NNODES];
__device__ int g_pak[EDGES];      // src | (code<<18)

// ---------------- helpers ----------------
__device__ __forceinline__ float hfr(float a) {
    return __half2float(__float2half_rn(a));
}
__device__ __forceinline__ uint32_t packhf(float e0, float e1) {
    uint32_t r;
    asm("cvt.rn.f16x2.f32 %0, %1, %2;" : "=r"(r) : "f"(e1), "f"(e0));
    return r;
}
__device__ __forceinline__ void mma_f16(float* c, const uint32_t* a, const uint32_t* b) {
    asm volatile(
        "mma.sync.aligned.m16n8k16.row.col.f32.f16.f16.f32 "
        "{%0,%1,%2,%3}, {%4,%5,%6,%7}, {%8,%9}, {%0,%1,%2,%3};"
        : "+f"(c[0]), "+f"(c[1]), "+f"(c[2]), "+f"(c[3])
        : "r"(a[0]), "r"(a[1]), "r"(a[2]), "r"(a[3]), "r"(b[0]), "r"(b[1]));
}

// ---------------- CSR build (once per call) ----------------
__global__ void zero_cnt_kernel() {
    int i = blockIdx.x * blockDim.x + threadIdx.x;
    if (i < NNODES) g_cnt[i] = 0;
}
__global__ void hist_kernel(const int* __restrict__ dst) {
    int e = blockIdx.x * blockDim.x + threadIdx.x;
    if (e < EDGES) atomicAdd(&g_cnt[__ldg(dst + e)], 1);
}
__global__ void scan_kernel() {
    __shared__ int part[1024];
    const int CH = (NNODES + 1023) / 1024;
    int t = threadIdx.x;
    int base = t * CH;
    int s = 0;
    for (int i = 0; i < CH; ++i) {
        int n = base + i;
        if (n < NNODES) s += g_cnt[n];
    }
    part[t] = s;
    __syncthreads();
    for (int off = 1; off < 1024; off <<= 1) {
        int tmp = (t >= off) ? part[t - off] : 0;
        __syncthreads();
        if (t >= off) part[t] += tmp;
        __syncthreads();
    }
    int run = part[t] - s;
    for (int i = 0; i < CH; ++i) {
        int n = base + i;
        if (n < NNODES) {
            g_off[n] = run;
            g_cur[n] = run;
            run += g_cnt[n];
        }
    }
    if (t == 0) g_off[NNODES] = EDGES;
}
__global__ void scatter_kernel(const int* __restrict__ src,
                               const int* __restrict__ dst,
                               const int* __restrict__ ea) {
    int e = blockIdx.x * blockDim.x + threadIdx.x;
    if (e >= EDGES) return;
    int d = __ldg(dst + e);
    int code = (__ldg(ea + 3 * e) * 6 + __ldg(ea + 3 * e + 1)) * 2 + __ldg(ea + 3 * e + 2);
    int pos = atomicAdd(&g_cur[d], 1);
    g_pak[pos] = __ldg(src + e) | (code << 18);
}

// all layers' combined bond tables in ONE launch (grid = LL*NCODE)
__global__ void bond_table_all_kernel(const float* __restrict__ bond) {
    int l    = blockIdx.x / NCODE;
    int code = blockIdx.x % NCODE;
    int d    = threadIdx.x;
    const float* b = bond + (size_t)l * BOND_ROWS * DD;
    int a0 = code / 12, a1 = (code / 2) % 6, a2 = code & 1;
    g_btab[((size_t)l * NCODE + code) * DD + d] =
          __ldg(b + (size_t)a0 * DD + d)
        + __ldg(b + (size_t)(5 + a1) * DD + d)
        + __ldg(b + (size_t)(11 + a2) * DD + d);
}

// agg[n] = (1+eps[l])*h[n] + sum_{CSR(n)} relu(h[src]+btab[l][code])
// One warp per node; 2-edge unrolled gather (MLP x2). Block 0 zeroes stats.
__global__ void __launch_bounds__(256)
aggregate_kernel(const float* __restrict__ h, const float* __restrict__ eps,
                 int l, float* __restrict__ agg) {
    if (blockIdx.x == 0) {
        int t = threadIdx.x;
        if (t < HH) { g_sum1[t] = 0.f; g_sq1[t] = 0.f; }
        if (t < DD) { g_sum2[t] = 0.f; g_sq2[t] = 0.f; }
    }
    int n    = (blockIdx.x * blockDim.x + threadIdx.x) >> 5;
    int lane = threadIdx.x & 31;
    if (n >= NNODES) return;
    const float* btab = g_btab + (size_t)l * NCODE * DD;

    int e0 = __ldg(g_off + n), e1 = __ldg(g_off + n + 1);
    float4 acc = make_float4(0.f, 0.f, 0.f, 0.f);
    int e = e0;
    for (; e + 1 < e1; e += 2) {
        int p0 = __ldg(g_pak + e);
        int p1 = __ldg(g_pak + e + 1);
        int s0 = p0 & 0x3FFFF, c0 = p0 >> 18;
        int s1 = p1 & 0x3FFFF, c1 = p1 >> 18;
        float4 v0  = __ldg((const float4*)(h + (size_t)s0 * DD) + lane);
        float4 v1  = __ldg((const float4*)(h + (size_t)s1 * DD) + lane);
        float4 t0  = __ldg((const float4*)(btab + (size_t)c0 * DD) + lane);
        float4 t1  = __ldg((const float4*)(btab + (size_t)c1 * DD) + lane);
        acc.x += fmaxf(v0.x + t0.x, 0.f) + fmaxf(v1.x + t1.x, 0.f);
        acc.y += fmaxf(v0.y + t0.y, 0.f) + fmaxf(v1.y + t1.y, 0.f);
        acc.z += fmaxf(v0.z + t0.z, 0.f) + fmaxf(v1.z + t1.z, 0.f);
        acc.w += fmaxf(v0.w + t0.w, 0.f) + fmaxf(v1.w + t1.w, 0.f);
    }
    if (e < e1) {
        int p = __ldg(g_pak + e);
        int s = p & 0x3FFFF, c = p >> 18;
        float4 v  = __ldg((const float4*)(h + (size_t)s * DD) + lane);
        float4 tb = __ldg((const float4*)(btab + (size_t)c * DD) + lane);
        acc.x += fmaxf(v.x + tb.x, 0.f);
        acc.y += fmaxf(v.y + tb.y, 0.f);
        acc.z += fmaxf(v.z + tb.z, 0.f);
        acc.w += fmaxf(v.w + tb.w, 0.f);
    }
    float ce = 1.f + __ldg(eps + l);
    float4 hv = __ldg((const float4*)(h + (size_t)n * DD) + lane);
    acc.x = fmaf(hv.x, ce, acc.x);
    acc.y = fmaf(hv.y, ce, acc.y);
    acc.z = fmaf(hv.z, ce, acc.z);
    acc.w = fmaf(hv.w, ce, acc.w);
    *((float4*)(agg + (size_t)n * DD) + lane) = acc;
}

// ------- 3x-f16 split tensor-core GEMM, double-buffered, fused stats -------
// C[M,NC] = act(A)[M,K] @ B[K,NC] + bias, act = BN1+ReLU when BNA.
// (R12 configuration: 128x128 tile, 8 warps 4m x 2n — the measured plateau.)
template<int K, int NC, bool BNA>
__global__ void __launch_bounds__(256, 2)
gemm_tc_kernel(const float* __restrict__ A, const float* __restrict__ B,
               const float* __restrict__ bias, float* __restrict__ C, int M,
               const float* __restrict__ bsum, const float* __restrict__ bsq,
               const float* __restrict__ gam,  const float* __restrict__ bet,
               float* __restrict__ osum, float* __restrict__ osq) {
    constexpr int BM = 128, BN = 128, BK = 16, K2 = BK / 2;
    constexpr int KS = BNA ? K : 1;
    __shared__ uint32_t AsH[2][K2][BM + 8];
    __shared__ uint32_t AsL[2][K2][BM + 8];
    __shared__ uint32_t BsH[2][K2][BN + 8];
    __shared__ uint32_t BsL[2][K2][BN + 8];
    __shared__ float ssc[KS], ssh[KS];

    int tid = threadIdx.x;
    if (BNA) {
        float invM = 1.f / (float)M;
        for (int k = tid; k < K; k += 256) {
            float mu  = bsum[k] * invM;
            float var = bsq[k] * invM - mu * mu;
            float s   = gam[k] * rsqrtf(var + 1e-5f);
            ssc[k] = s;
            ssh[k] = bet[k] - mu * s;
        }
        __syncthreads();
    }

    int bm = blockIdx.x * BM;
    int bn = blockIdx.y * BN;
    int lane = tid & 31;
    int warp = tid >> 5;
    int wm = (warp & 3) * 32;
    int wn = (warp >> 2) * 64;
    int g = lane >> 2;
    int t = lane & 3;

    float acc[2][8][4];
#pragma unroll
    for (int mi = 0; mi < 2; ++mi)
#pragma unroll
        for (int ni = 0; ni < 8; ++ni)
#pragma unroll
            for (int j = 0; j < 4; ++j) acc[mi][ni][j] = 0.f;

    const int k2r = tid >> 5;
    const int cg  = tid & 31;
    const int rA0 = (tid * 2)     >> 2, cA0 = (tid * 2)     & 3;
    const int rA1 = (tid * 2 + 1) >> 2, cA1 = (tid * 2 + 1) & 3;

    float4 pa[2], pb0, pb1;

    auto ldg_tile = [&](int k0) {
        int gr0 = bm + rA0, gr1 = bm + rA1;
        pa[0] = (gr0 < M) ? __ldg((const float4*)(A + (size_t)gr0 * K + k0 + cA0 * 4))
                          : make_float4(0.f, 0.f, 0.f, 0.f);
        pa[1] = (gr1 < M) ? __ldg((const float4*)(A + (size_t)gr1 * K + k0 + cA1 * 4))
                          : make_float4(0.f, 0.f, 0.f, 0.f);
        pb0 = __ldg((const float4*)(B + (size_t)(k0 + 2 * k2r)     * NC + bn + cg * 4));
        pb1 = __ldg((const float4*)(B + (size_t)(k0 + 2 * k2r + 1) * NC + bn + cg * 4));
    };

    auto store_tile = [&](int s, int k0) {
#pragma unroll
        for (int it = 0; it < 2; ++it) {
            int r  = it ? rA1 : rA0;
            int c4 = it ? cA1 : cA0;
            float4 v = pa[it];
            if (BNA) {
                int kk = k0 + c4 * 4;
                v.x = fmaxf(fmaf(v.x, ssc[kk + 0], ssh[kk + 0]), 0.f);
                v.y = fmaxf(fmaf(v.y, ssc[kk + 1], ssh[kk + 1]), 0.f);
                v.z = fmaxf(fmaf(v.z, ssc[kk + 2], ssh[kk + 2]), 0.f);
                v.w = fmaxf(fmaf(v.w, ssc[kk + 3], ssh[kk + 3]), 0.f);
            }
            float h0 = hfr(v.x), h1 = hfr(v.y), h2 = hfr(v.z), h3 = hfr(v.w);
            AsH[s][c4 * 2 + 0][r] = packhf(h0, h1);
            AsH[s][c4 * 2 + 1][r] = packhf(h2, h3);
            AsL[s][c4 * 2 + 0][r] = packhf(v.x - h0, v.y - h1);
            AsL[s][c4 * 2 + 1][r] = packhf(v.z - h2, v.w - h3);
        }
        float bh0 = hfr(pb0.x), bh1 = hfr(pb0.y), bh2 = hfr(pb0.z), bh3 = hfr(pb0.w);
        float ch0 = hfr(pb1.x), ch1 = hfr(pb1.y), ch2 = hfr(pb1.z), ch3 = hfr(pb1.w);
        uint4 uh, ul;
        uh.x = packhf(bh0, ch0); uh.y = packhf(bh1, ch1);
        uh.z = packhf(bh2, ch2); uh.w = packhf(bh3, ch3);
        ul.x = packhf(pb0.x - bh0, pb1.x - ch0);
        ul.y = packhf(pb0.y - bh1, pb1.y - ch1);
        ul.z = packhf(pb0.z - bh2, pb1.z - ch2);
        ul.w = packhf(pb0.w - bh3, pb1.w - ch3);
        *(uint4*)&BsH[s][k2r][cg * 4] = uh;
        *(uint4*)&BsL[s][k2r][cg * 4] = ul;
    };

    ldg_tile(0);
    store_tile(0, 0);
    __syncthreads();

    int s = 0;
    for (int k0 = 0; k0 < K; k0 += BK) {
        int kn = k0 + BK;
        if (kn < K) ldg_tile(kn);

        uint32_t ah[2][4], al[2][4];
#pragma unroll
        for (int mi = 0; mi < 2; ++mi) {
            int row = wm + mi * 16 + g;
            ah[mi][0] = AsH[s][t][row];     ah[mi][1] = AsH[s][t][row + 8];
            ah[mi][2] = AsH[s][t + 4][row]; ah[mi][3] = AsH[s][t + 4][row + 8];
            al[mi][0] = AsL[s][t][row];     al[mi][1] = AsL[s][t][row + 8];
            al[mi][2] = AsL[s][t + 4][row]; al[mi][3] = AsL[s][t + 4][row + 8];
        }
        uint32_t bh[8][2], bl[8][2];
#pragma unroll
        for (int ni = 0; ni < 8; ++ni) {
            int col = wn + ni * 8 + g;
            bh[ni][0] = BsH[s][t][col]; bh[ni][1] = BsH[s][t + 4][col];
            bl[ni][0] = BsL[s][t][col]; bl[ni][1] = BsL[s][t + 4][col];
        }
#pragma unroll
        for (int ni = 0; ni < 8; ++ni)
#pragma unroll
            for (int mi = 0; mi < 2; ++mi)
                mma_f16(acc[mi][ni], ah[mi], bl[ni]);
#pragma unroll
        for (int ni = 0; ni < 8; ++ni)
#pragma unroll
            for (int mi = 0; mi < 2; ++mi)
                mma_f16(acc[mi][ni], al[mi], bh[ni]);
#pragma unroll
        for (int ni = 0; ni < 8; ++ni)
#pragma unroll
            for (int mi = 0; mi < 2; ++mi)
                mma_f16(acc[mi][ni], ah[mi], bh[ni]);

        if (kn < K) store_tile(s ^ 1, kn);
        __syncthreads();
        s ^= 1;
    }

#pragma unroll
    for (int ni = 0; ni < 8; ++ni) {
        int col = bn + wn + ni * 8 + 2 * t;
        float bx = __ldg(bias + col), by = __ldg(bias + col + 1);
        float s0 = 0.f, q0 = 0.f, s1 = 0.f, q1 = 0.f;
#pragma unroll
        for (int mi = 0; mi < 2; ++mi) {
            int row0 = bm + wm + mi * 16 + g;
            int row1 = row0 + 8;
            if (row0 < M) {
                float v0 = acc[mi][ni][0] + bx;
                float v1 = acc[mi][ni][1] + by;
                *(float2*)(C + (size_t)row0 * NC + col) = make_float2(v0, v1);
                s0 += v0; q0 = fmaf(v0, v0, q0);
                s1 += v1; q1 = fmaf(v1, v1, q1);
            }
            if (row1 < M) {
                float v2 = acc[mi][ni][2] + bx;
                float v3 = acc[mi][ni][3] + by;
                *(float2*)(C + (size_t)row1 * NC + col) = make_float2(v2, v3);
                s0 += v2; q0 = fmaf(v2, v2, q0);
                s1 += v3; q1 = fmaf(v3, v3, q1);
            }
        }
#pragma unroll
        for (int o = 4; o < 32; o <<= 1) {
            s0 += __shfl_xor_sync(0xFFFFFFFF, s0, o);
            q0 += __shfl_xor_sync(0xFFFFFFFF, q0, o);
            s1 += __shfl_xor_sync(0xFFFFFFFF, s1, o);
            q1 += __shfl_xor_sync(0xFFFFFFFF, q1, o);
        }
        if (g == 0) {
            atomicAdd(osum + col,     s0);
            atomicAdd(osq  + col,     q0);
            atomicAdd(osum + col + 1, s1);
            atomicAdd(osq  + col + 1, q1);
        }
    }
}

// out = bn2(z2) [+ relu]; smem-staged scale/shift
__global__ void __launch_bounds__(256)
bn2_apply_kernel(const float* __restrict__ z,
                 float* __restrict__ out,
                 const float* __restrict__ gam,
                 const float* __restrict__ bet,
                 int do_relu, float invM) {
    __shared__ float sc[DD], sh[DD];
    int tid = threadIdx.x;
    if (tid < DD) {
        float mu  = g_sum2[tid] * invM;
        float var = g_sq2[tid] * invM - mu * mu;
        float s   = __ldg(gam + tid) * rsqrtf(var + 1e-5f);
        sc[tid] = s;
        sh[tid] = __ldg(bet + tid) - mu * s;
    }
    __syncthreads();
    const int n4 = NNODES * DD / 4;
    int base = blockIdx.x * 1024;
#pragma unroll
    for (int j = 0; j < 4; ++j) {
        int i = base + j * 256 + tid;
        if (i >= n4) break;
        int c = (i & (DD / 4 - 1)) << 2;
        float4 v = __ldg((const float4*)z + i);
        v.x = fmaf(v.x, sc[c + 0], sh[c + 0]);
        v.y = fmaf(v.y, sc[c + 1], sh[c + 1]);
        v.z = fmaf(v.z, sc[c + 2], sh[c + 2]);
        v.w = fmaf(v.w, sc[c + 3], sh[c + 3]);
        if (do_relu) {
            v.x = fmaxf(v.x, 0.f); v.y = fmaxf(v.y, 0.f);
            v.z = fmaxf(v.z, 0.f); v.w = fmaxf(v.w, 0.f);
        }
        ((float4*)out)[i] = v;
    }
}

// ---------------- host launcher ----------------
extern "C" void kernel_launch(void* const* d_in, const int* in_sizes, int n_in,
                              void* d_out, int out_size) {
    const float* x    = (const float*)d_in[0];
    const int*   ei   = (const int*)  d_in[1];
    const int*   ea   = (const int*)  d_in[2];
    const float* W1   = (const float*)d_in[3];
    const float* b1   = (const float*)d_in[4];
    const float* g1   = (const float*)d_in[5];
    const float* bb1  = (const float*)d_in[6];
    const float* W2   = (const float*)d_in[7];
    const float* b2   = (const float*)d_in[8];
    const float* eps  = (const float*)d_in[9];
    const float* bond = (const float*)d_in[10];
    const float* g2   = (const float*)d_in[11];
    const float* bb2  = (const float*)d_in[12];
    float* out = (float*)d_out;

    float *p_agg, *p_y, *p_z2, *p_h;
    float *p_sum1, *p_sq1, *p_sum2, *p_sq2;
    cudaGetSymbolAddress((void**)&p_agg,  g_agg);
    cudaGetSymbolAddress((void**)&p_y,    g_y);
    cudaGetSymbolAddress((void**)&p_z2,   g_z2);
    cudaGetSymbolAddress((void**)&p_h,    g_h);
    cudaGetSymbolAddress((void**)&p_sum1, g_sum1);
    cudaGetSymbolAddress((void**)&p_sq1,  g_sq1);
    cudaGetSymbolAddress((void**)&p_sum2, g_sum2);
    cudaGetSymbolAddress((void**)&p_sq2,  g_sq2);

    const int M = NNODES;
    const int agg_blocks = (NNODES * 32 + 255) / 256;
    const int bn_blocks  = (NNODES * DD / 4 + 1023) / 1024;
    const dim3 g1grid((M + 127) / 128, HH / 128);   // 391 x 2
    const dim3 g2grid((M + 127) / 128, DD / 128);   // 391 x 1
    const float invM = 1.f / (float)M;

    // ---- one-time preamble: CSR build + ALL bond tables ----
    zero_cnt_kernel<<<(NNODES + 255) / 256, 256>>>();
    hist_kernel<<<(EDGES + 255) / 256, 256>>>(ei + EDGES);
    scan_kernel<<<1, 1024>>>();
    scatter_kernel<<<(EDGES + 255) / 256, 256>>>(ei, ei + EDGES, ea);
    bond_table_all_kernel<<<LL * NCODE, DD>>>(bond);

    const float* hcur = x;
    for (int l = 0; l < LL; ++l) {
        aggregate_kernel<<<agg_blocks, 256>>>(hcur, eps, l, p_agg);
        // GEMM1 (3x-f16 TC, fused BN1 stats): y = agg @ W1[l] + b1[l]
        gemm_tc_kernel<DD, HH, false><<<g1grid, 256>>>(
            p_agg, W1 + (size_t)l * DD * HH, b1 + (size_t)l * HH, p_y, M,
            nullptr, nullptr, nullptr, nullptr, p_sum1, p_sq1);
        // GEMM2 (3x-f16 TC, fused BN1+ReLU on A, fused BN2 stats)
        gemm_tc_kernel<HH, DD, true><<<g2grid, 256>>>(
            p_y, W2 + (size_t)l * HH * DD, b2 + (size_t)l * DD, p_z2, M,
            p_sum1, p_sq1, g1 + (size_t)l * HH, bb1 + (size_t)l * HH,
            p_sum2, p_sq2);
        bool last = (l == LL - 1);
        bn2_apply_kernel<<<bn_blocks, 256>>>(
            p_z2, last ? out : p_h,
            g2 + (size_t)l * DD, bb2 + (size_t)l * DD,
            last ? 0 : 1, invM);
        hcur = p_h;
    }
}